// round 8
// baseline (speedup 1.0000x reference)
#include <cuda_runtime.h>
#include <math.h>
#include <stdint.h>

#define HH    64
#define DIMC  512     // per-axis sinusoid width
#define ODIM  256     // output dim
#define BATCH 8
#define NSPLIT 16     // split-K partials

// Partial sums: g_Cpart[kc][r][o]; r<64 -> A-half (W cols 0:512), r>=64 -> B-half.
// Plain overwrite stores every launch -> no zeroing, no atomics, no state.
__device__ float g_Cpart[NSPLIT][2 * HH][ODIM];   // 2 MB
__device__ float g_C[2 * HH][ODIM];               // reduced result (128 KB)

// ---------------------------------------------------------------------------
// k1: fused embed + split-K GEMM partials (plain stores), 512 threads.
//   Cpart[kc][half*64+m][o] = sum_{k in chunk kc} embed(m)[k] * W[o][half*512+k]
// grid (16 kc, 4 ntiles, 2 halves) = 128 blocks x 512 threads (16 warps/SM).
// ---------------------------------------------------------------------------
__global__ __launch_bounds__(512) void k1_embed_gemm(const float* __restrict__ W) {
    const int kc   = blockIdx.x;
    const int k0   = kc * 32;
    const int n0   = blockIdx.y * 64;
    const int half = blockIdx.z;
    const int off  = half * DIMC;

    __shared__ float fr[32];
    __shared__ float Es[64][36];
    __shared__ float Ws[32][68];

    const int t = threadIdx.x;

    if (t < 32) {
        int c = k0 + t;
        float expo = (c < 256) ? (float)(2 * c + 1) * (1.0f / 512.0f)
                               : (float)(2 * (c - 256)) * (1.0f / 512.0f);
        fr[t] = __expf(-expo * 6.907755278982137f);   // 1000^(-expo)
    }
    __syncthreads();

    // 2048 elements over 512 threads: 4 each
    #pragma unroll
    for (int e = t; e < 64 * 32; e += 512) {
        int kk = e & 31, m = e >> 5;
        float zf = (float)m * fr[kk];
        Es[m][kk] = (k0 + kk < 256) ? __sinf(zf) : __cosf(zf);
    }
    #pragma unroll
    for (int e = t; e < 64 * 32; e += 512) {
        int kk = e & 31, i = e >> 5;
        Ws[kk][i] = W[(size_t)(n0 + i) * (2 * DIMC) + off + k0 + kk];
    }
    __syncthreads();

    const int tx = t & 31, ty = t >> 5;    // 32 x 16 threads
    const int mb = ty * 4, nb = tx * 2;    // 4x2 micro-tile

    float acc[4][2] = {};
    #pragma unroll 8
    for (int k = 0; k < 32; k++) {
        float b0 = Ws[k][nb], b1 = Ws[k][nb + 1];
        float a0 = Es[mb + 0][k];
        float a1 = Es[mb + 1][k];
        float a2 = Es[mb + 2][k];
        float a3 = Es[mb + 3][k];
        acc[0][0] += a0 * b0; acc[0][1] += a0 * b1;
        acc[1][0] += a1 * b0; acc[1][1] += a1 * b1;
        acc[2][0] += a2 * b0; acc[2][1] += a2 * b1;
        acc[3][0] += a3 * b0; acc[3][1] += a3 * b1;
    }

    const int rbase = half * 64 + mb;
    #pragma unroll
    for (int i = 0; i < 4; i++) {
        float2 v = make_float2(acc[i][0], acc[i][1]);
        *(float2*)&g_Cpart[kc][rbase + i][n0 + nb] = v;
    }
}

// ---------------------------------------------------------------------------
// k1b: reduce 16 partials -> g_C. 8192 float4 slots, 64 blocks x 128 thr.
// Coalesced LDG.128, MLP=16, plain stores. Stateless.
// ---------------------------------------------------------------------------
__global__ __launch_bounds__(128) void k1b_reduce() {
    const int idx = blockIdx.x * 128 + threadIdx.x;     // 0..8191
    const float4* p = (const float4*)g_Cpart;
    const int stride = (2 * HH * ODIM) / 4;             // 8192 float4 per partial

    float4 s = p[idx];
    #pragma unroll
    for (int k = 1; k < NSPLIT; k++) {
        float4 v = p[idx + k * stride];
        s.x += v.x; s.y += v.y; s.z += v.z; s.w += v.w;
    }
    ((float4*)g_C)[idx] = s;
}

// ---------------------------------------------------------------------------
// k2: broadcast write, read-amortized further.
//   out[b][h][w][o] = C[h][o] + C[64+w][o]
// block (h, wq): h fixed, w in [wq*16, wq*16+16), ALL 8 batches.
// Reads 17 KB of C per block -> total C reads 4.4 MB (was 9.2).
// grid (64, 4) = 256 blocks x 256 threads; 32 coalesced STG.128 per thread.
// ---------------------------------------------------------------------------
__global__ __launch_bounds__(256) void k2_write(float* __restrict__ out) {
    const int t  = threadIdx.x;
    const int q  = t & 63;        // float4 column (o = 4q)
    const int rg = t >> 6;        // 0..3 -> 4 w-rows each
    const int h  = blockIdx.x;    // 0..63
    const int wq = blockIdx.y;    // 0..3

    const size_t colo = (size_t)q * 4;
    float4 a = *(const float4*)&g_C[h][colo];

    #pragma unroll
    for (int i = 0; i < 4; i++) {
        int w = wq * 16 + rg * 4 + i;
        float4 e = *(const float4*)&g_C[64 + w][colo];
        float4 v;
        v.x = a.x + e.x; v.y = a.y + e.y; v.z = a.z + e.z; v.w = a.w + e.w;

        size_t base = (((size_t)h * HH + w) * ODIM) + colo;
        const size_t bstride = (size_t)HH * HH * ODIM;
        #pragma unroll
        for (int b = 0; b < BATCH; b++)
            *(float4*)&out[base + (size_t)b * bstride] = v;
    }
}

// ---------------------------------------------------------------------------
extern "C" void kernel_launch(void* const* d_in, const int* in_sizes, int n_in,
                              void* d_out, int out_size) {
    const float* W = (const float*)d_in[0];   // W_im: (256, 1024) fp32
    float* out = (float*)d_out;               // (8, 64, 64, 256, 1) fp32

    dim3 g1(NSPLIT, 4, 2);
    k1_embed_gemm<<<g1, 512>>>(W);
    k1b_reduce<<<64, 128>>>();
    dim3 g2(HH, 4);
    k2_write<<<g2, 256>>>(out);
}